// round 12
// baseline (speedup 1.0000x reference)
#include <cuda_runtime.h>
#include <cuda_bf16.h>
#include <cstddef>
#include <cstdint>

// GodelToposEngine: next = clamp(R @ prev, 0, 1), up to 20 steps.
// status: 1=PROVEN (next==prev), 2=GODEL (next==pprev, step>=2), 3=TIMEOUT.
// allclose: |a-b| <= atol + rtol*|b|, atol=1e-4, rtol=1e-5 (b = second arg).

#define NN 8192
#define MAXS 20
#define ATOL 1e-4f
#define RTOL 1e-5f

#define CPS 256                 // columns per pipeline stage (floats) = 1 KB
#define NSTAGE (NN / CPS)       // 32 stages
#define NSLOT 4                 // ring depth (wait_group 3 => ~3-4 KB in flight/warp)

// Triple-buffered state vectors + control scalars (no allocation allowed).
__device__ float g_buf[3][NN];
__device__ int g_status;
__device__ int g_steps;
__device__ int g_final;   // which buffer holds the final state
__device__ int g_viol1;   // any element violates allclose(next, prev)
__device__ int g_viol2;   // any element violates allclose(next, pprev)

__global__ void __launch_bounds__(256) init_kernel(const float* __restrict__ sv) {
    int idx = blockIdx.x * 256 + threadIdx.x;   // grid 32x256 = 8192
    float v = sv[idx];
    g_buf[0][idx] = v;   // prev  for step 1
    g_buf[2][idx] = v;   // pprev for step 1
    if (idx == 0) {
        g_status = 0;
        g_steps = 0;
        g_final = 2;
        g_viol1 = 0;
        g_viol2 = 0;
    }
}

__device__ __forceinline__ void cp16(uint32_t dst, const float* src) {
    // .cg: L2-only — keep L1 free for the x vector.
    asm volatile("cp.async.cg.shared.global [%0], [%1], 16;" :: "r"(dst), "l"(src));
}
__device__ __forceinline__ void cp_commit() {
    asm volatile("cp.async.commit_group;" ::: "memory");
}
__device__ __forceinline__ void cp_wait3() {
    asm volatile("cp.async.wait_group 3;" ::: "memory");
}

// One step: GEMV + clamp + convergence flags.
// 1024 blocks x 256 threads, warp-per-row, cp.async 4-slot ring per warp.
// 1024 blocks at 7 blocks/SM residency -> one wave, imbalance 7/6.92=1.012
// (vs 4/3.46=1.16 at 512 blocks, which capped DRAM at ~72%). Each lane reads
// back only the smem bytes it itself copied -> NO barriers, only wait_group.
__global__ void __launch_bounds__(256, 7) gemv_step(const float* __restrict__ R,
                                                    int pi, int ppi, int ni) {
    if (g_status != 0) return;   // frozen: skip all work

    // [warp][slot][chunk] : 8*4*64 float4 = 32 KB (7 blocks * 32 KB <= 228 KB)
    __shared__ float4 smem[8][NSLOT][CPS / 4];

    const int tid  = threadIdx.x;
    const int warp = tid >> 5;
    const int lane = tid & 31;
    const int row  = blockIdx.x * 8 + warp;   // [0, 8192)

    const uint32_t sbase =
        (uint32_t)__cvta_generic_to_shared(&smem[warp][0][0]);
    const float* __restrict__ rp = R + (size_t)row * NN;
    const float4* __restrict__ xp = (const float4*)g_buf[pi];

    // Prologue: stages 0..NSLOT-1 in flight (one group per stage).
#pragma unroll
    for (int s = 0; s < NSLOT; s++) {
        uint32_t sb = sbase + (uint32_t)s * (CPS * 4);
        cp16(sb + lane * 16,              rp + s * CPS + lane * 4);
        cp16(sb + (lane + 32) * 16,       rp + s * CPS + (lane + 32) * 4);
        cp_commit();
    }

    float ax = 0.f, ay = 0.f, az = 0.f, aw = 0.f;

    int slot = 0;
#pragma unroll 1
    for (int s = 0; s < NSTAGE; s++) {
        cp_wait3();                      // stage s landed (<=3 groups pending)
        const float4* sm = &smem[warp][slot][0];
#pragma unroll
        for (int k = 0; k < 2; k++) {
            int c = lane + 32 * k;
            float4 b = __ldg(xp + s * (CPS / 4) + c);   // L1-resident x
            float4 a = sm[c];
            ax += a.x * b.x;
            ay += a.y * b.y;
            az += a.z * b.z;
            aw += a.w * b.w;
        }
        // Refill this slot with stage s+NSLOT (commit every iteration to
        // keep the one-group-per-iteration accounting exact).
        if (s + NSLOT < NSTAGE) {
            uint32_t sb = sbase + (uint32_t)slot * (CPS * 4);
            int sc = (s + NSLOT) * CPS;
            cp16(sb + lane * 16,        rp + sc + lane * 4);
            cp16(sb + (lane + 32) * 16, rp + sc + (lane + 32) * 4);
        }
        cp_commit();
        slot = (slot + 1) & (NSLOT - 1);
    }

    float s = (ax + ay) + (az + aw);
#pragma unroll
    for (int o = 16; o; o >>= 1) s += __shfl_xor_sync(0xFFFFFFFFu, s, o);

    if (lane == 0) {
        float v = fminf(fmaxf(s, 0.0f), 1.0f);
        g_buf[ni][row] = v;
        float p  = g_buf[pi][row];
        float pp = g_buf[ppi][row];
        if (fabsf(v - p)  > ATOL + RTOL * fabsf(p))  atomicOr(&g_viol1, 1);
        if (fabsf(v - pp) > ATOL + RTOL * fabsf(pp)) atomicOr(&g_viol2, 1);
    }
}

// Per-step status update (frozen-carry semantics of the reference scan).
__global__ void update_step(int k, int ni) {
    if (g_status == 0) {
        g_steps = k;
        g_final = ni;
        if (g_viol1 == 0)                g_status = 1;  // PROVEN (priority)
        else if (k >= 2 && g_viol2 == 0) g_status = 2;  // GODEL
    }
    g_viol1 = 0;
    g_viol2 = 0;
}

__global__ void __launch_bounds__(256) final_kernel(float* __restrict__ out,
                                                    int out_size) {
    int idx = blockIdx.x * 256 + threadIdx.x;   // grid 32x256 = 8192
    int fi = g_final;
    if (idx < NN && idx < out_size) out[idx] = g_buf[fi][idx];
    if (idx == 0 && out_size >= NN + 2) {
        int st = g_status;
        out[NN]     = (float)(st == 0 ? 3 : st);   // TIMEOUT fixup
        out[NN + 1] = (float)g_steps;
    }
}

extern "C" void kernel_launch(void* const* d_in, const int* in_sizes, int n_in,
                              void* d_out, int out_size) {
    const float* R  = (const float*)d_in[0];
    const float* sv = (const float*)d_in[1];
    float* out = (float*)d_out;

    init_kernel<<<32, 256>>>(sv);
    for (int k = 1; k <= MAXS; k++) {
        int pi  = (k - 1) % 3;   // prev
        int ppi = (k + 1) % 3;   // pprev  ((k-2) mod 3, kept non-negative)
        int ni  = k % 3;         // next
        gemv_step<<<1024, 256>>>(R, pi, ppi, ni);
        update_step<<<1, 1>>>(k, ni);
    }
    final_kernel<<<32, 256>>>(out, out_size);
}

// round 13
// speedup vs baseline: 1.2145x; 1.2145x over previous
#include <cuda_runtime.h>
#include <cuda_bf16.h>
#include <cstddef>
#include <cstdint>

// GodelToposEngine: next = clamp(R @ prev, 0, 1), up to 20 steps.
// status: 1=PROVEN (next==prev), 2=GODEL (next==pprev, step>=2), 3=TIMEOUT.
// allclose: |a-b| <= atol + rtol*|b|, atol=1e-4, rtol=1e-5 (b = second arg).

#define NN 8192
#define MAXS 20
#define ATOL 1e-4f
#define RTOL 1e-5f

#define CPS 256                 // columns per pipeline stage (floats) = 1 KB
#define NSTAGE (NN / CPS)       // 32 stages
#define NSLOT 3                 // ring depth (wait_group 2 => ~2-3 KB in flight/warp)

// Triple-buffered state vectors + control scalars (no allocation allowed).
__device__ float g_buf[3][NN];
__device__ int g_status;
__device__ int g_steps;
__device__ int g_final;   // which buffer holds the final state
__device__ int g_viol1;   // any element violates allclose(next, prev)
__device__ int g_viol2;   // any element violates allclose(next, pprev)

__global__ void __launch_bounds__(256) init_kernel(const float* __restrict__ sv) {
    int idx = blockIdx.x * 256 + threadIdx.x;   // grid 32x256 = 8192
    float v = sv[idx];
    g_buf[0][idx] = v;   // prev  for step 1
    g_buf[2][idx] = v;   // pprev for step 1
    if (idx == 0) {
        g_status = 0;
        g_steps = 0;
        g_final = 2;
        g_viol1 = 0;
        g_viol2 = 0;
    }
}

__device__ __forceinline__ void cp16(uint32_t dst, const float* src) {
    // .cg: L2-only — keep L1 free for the x vector.
    asm volatile("cp.async.cg.shared.global [%0], [%1], 16;" :: "r"(dst), "l"(src));
}
__device__ __forceinline__ void cp_commit() {
    asm volatile("cp.async.commit_group;" ::: "memory");
}
__device__ __forceinline__ void cp_wait2() {
    asm volatile("cp.async.wait_group 2;" ::: "memory");
}

// One step: GEMV + clamp + convergence flags.
// 1024 blocks x 256 threads, warp-per-row, cp.async 3-slot ring per warp.
// Smem = 24 KB static (+1 KB driver reserve = 25 KB/block, learned in R12:
// the driver reserve is real and cost a residency slot at 32 KB). With
// launch_bounds(256,7): 7 blocks/SM -> capacity 1036 >= 1024 -> ONE wave,
// imbalance 1.012 (vs 1.16 at 512 blocks which capped DRAM at ~72%).
// Each lane reads back only smem bytes it itself copied -> NO barriers.
__global__ void __launch_bounds__(256, 7) gemv_step(const float* __restrict__ R,
                                                    int pi, int ppi, int ni) {
    if (g_status != 0) return;   // frozen: skip all work

    // [warp][slot][chunk] : 8*3*64 float4 = 24576 B
    __shared__ float4 smem[8][NSLOT][CPS / 4];

    const int tid  = threadIdx.x;
    const int warp = tid >> 5;
    const int lane = tid & 31;
    const int row  = blockIdx.x * 8 + warp;   // [0, 8192)

    const uint32_t sbase =
        (uint32_t)__cvta_generic_to_shared(&smem[warp][0][0]);
    const float* __restrict__ rp = R + (size_t)row * NN;
    const float4* __restrict__ xp = (const float4*)g_buf[pi];

    // Prologue: stages 0..NSLOT-1 in flight (one group per stage).
#pragma unroll
    for (int s = 0; s < NSLOT; s++) {
        uint32_t sb = sbase + (uint32_t)s * (CPS * 4);
        cp16(sb + lane * 16,        rp + s * CPS + lane * 4);
        cp16(sb + (lane + 32) * 16, rp + s * CPS + (lane + 32) * 4);
        cp_commit();
    }

    float ax = 0.f, ay = 0.f, az = 0.f, aw = 0.f;

    int slot = 0;
#pragma unroll 1
    for (int s = 0; s < NSTAGE; s++) {
        cp_wait2();                      // stage s landed (<=2 groups pending)
        const float4* sm = &smem[warp][slot][0];
#pragma unroll
        for (int k = 0; k < 2; k++) {
            int c = lane + 32 * k;
            float4 b = __ldg(xp + s * (CPS / 4) + c);   // L1-resident x
            float4 a = sm[c];
            ax += a.x * b.x;
            ay += a.y * b.y;
            az += a.z * b.z;
            aw += a.w * b.w;
        }
        // Refill this slot with stage s+NSLOT (commit every iteration to
        // keep the one-group-per-iteration accounting exact).
        if (s + NSLOT < NSTAGE) {
            uint32_t sb = sbase + (uint32_t)slot * (CPS * 4);
            int sc = (s + NSLOT) * CPS;
            cp16(sb + lane * 16,        rp + sc + lane * 4);
            cp16(sb + (lane + 32) * 16, rp + sc + (lane + 32) * 4);
        }
        cp_commit();
        slot = (slot + 1 == NSLOT) ? 0 : slot + 1;
    }

    float s = (ax + ay) + (az + aw);
#pragma unroll
    for (int o = 16; o; o >>= 1) s += __shfl_xor_sync(0xFFFFFFFFu, s, o);

    if (lane == 0) {
        float v = fminf(fmaxf(s, 0.0f), 1.0f);
        g_buf[ni][row] = v;
        float p  = g_buf[pi][row];
        float pp = g_buf[ppi][row];
        if (fabsf(v - p)  > ATOL + RTOL * fabsf(p))  atomicOr(&g_viol1, 1);
        if (fabsf(v - pp) > ATOL + RTOL * fabsf(pp)) atomicOr(&g_viol2, 1);
    }
}

// Per-step status update (frozen-carry semantics of the reference scan).
__global__ void update_step(int k, int ni) {
    if (g_status == 0) {
        g_steps = k;
        g_final = ni;
        if (g_viol1 == 0)                g_status = 1;  // PROVEN (priority)
        else if (k >= 2 && g_viol2 == 0) g_status = 2;  // GODEL
    }
    g_viol1 = 0;
    g_viol2 = 0;
}

__global__ void __launch_bounds__(256) final_kernel(float* __restrict__ out,
                                                    int out_size) {
    int idx = blockIdx.x * 256 + threadIdx.x;   // grid 32x256 = 8192
    int fi = g_final;
    if (idx < NN && idx < out_size) out[idx] = g_buf[fi][idx];
    if (idx == 0 && out_size >= NN + 2) {
        int st = g_status;
        out[NN]     = (float)(st == 0 ? 3 : st);   // TIMEOUT fixup
        out[NN + 1] = (float)g_steps;
    }
}

extern "C" void kernel_launch(void* const* d_in, const int* in_sizes, int n_in,
                              void* d_out, int out_size) {
    const float* R  = (const float*)d_in[0];
    const float* sv = (const float*)d_in[1];
    float* out = (float*)d_out;

    init_kernel<<<32, 256>>>(sv);
    for (int k = 1; k <= MAXS; k++) {
        int pi  = (k - 1) % 3;   // prev
        int ppi = (k + 1) % 3;   // pprev  ((k-2) mod 3, kept non-negative)
        int ni  = k % 3;         // next
        gemv_step<<<1024, 256>>>(R, pi, ppi, ni);
        update_step<<<1, 1>>>(k, ni);
    }
    final_kernel<<<32, 256>>>(out, out_size);
}

// round 14
// speedup vs baseline: 1.3186x; 1.0857x over previous
#include <cuda_runtime.h>
#include <cuda_bf16.h>
#include <cstddef>
#include <cstdint>

// GodelToposEngine: next = clamp(R @ prev, 0, 1), up to 20 steps.
// status: 1=PROVEN (next==prev), 2=GODEL (next==pprev, step>=2), 3=TIMEOUT.
// allclose: |a-b| <= atol + rtol*|b|, atol=1e-4, rtol=1e-5 (b = second arg).

#define NN 8192
#define MAXS 20
#define ATOL 1e-4f
#define RTOL 1e-5f

#define CPS 256                 // columns per pipeline stage (floats)
#define NSTAGE (NN / CPS)       // 32 stages
#define NSLOT 3                 // ring depth (wait_group 2)

// Triple-buffered state vectors + control scalars (no allocation allowed).
__device__ float g_buf[3][NN];
__device__ int g_status;
__device__ int g_steps;
__device__ int g_final;   // which buffer holds the final state
__device__ int g_viol1;   // any element violates allclose(next, prev)
__device__ int g_viol2;   // any element violates allclose(next, pprev)

__global__ void __launch_bounds__(256) init_kernel(const float* __restrict__ sv) {
    int idx = blockIdx.x * 256 + threadIdx.x;   // grid 32x256 = 8192
    float v = sv[idx];
    g_buf[0][idx] = v;   // prev  for step 1
    g_buf[2][idx] = v;   // pprev for step 1
    if (idx == 0) {
        g_status = 0;
        g_steps = 0;
        g_final = 2;
        g_viol1 = 0;
        g_viol2 = 0;
    }
}

__device__ __forceinline__ void cp16(uint32_t dst, const float* src) {
    // .cg: L2-only — keep L1 free for the x vector.
    asm volatile("cp.async.cg.shared.global [%0], [%1], 16;" :: "r"(dst), "l"(src));
}
__device__ __forceinline__ void cp_commit() {
    asm volatile("cp.async.commit_group;" ::: "memory");
}
__device__ __forceinline__ void cp_wait2() {
    asm volatile("cp.async.wait_group 2;" ::: "memory");
}

// One step: GEMV + clamp + convergence flags.
// 1024 blocks x 128 threads (4 warps); warp owns 2 adjacent rows — the exact
// R11 inner loop. Key change: 128-thread blocks decouple warp load from wave
// balance. 8 blocks/SM capacity (regs<=64, smem 24+1 KB) -> one wave at
// ~28 warps/SM (R7's sweet spot, avoiding the 56-warp L1tex-queue spread of
// R13) with warp imbalance 28/27.68 = 1.012 (vs R7's block imbalance 1.16).
// Each lane reads back only smem bytes it itself copied -> NO barriers.
__global__ void __launch_bounds__(128, 8) gemv_step(const float* __restrict__ R,
                                                    int pi, int ppi, int ni) {
    if (g_status != 0) return;   // frozen: skip all work

    // [warp][slot][row][chunk] : 4*3*2*64 float4 = 24576 B
    __shared__ float4 smem[4][NSLOT][2][CPS / 4];

    const int tid  = threadIdx.x;
    const int warp = tid >> 5;
    const int lane = tid & 31;
    const int w    = blockIdx.x * 4 + warp;   // [0, 4096)
    const int row0 = 2 * w;

    const uint32_t sbase =
        (uint32_t)__cvta_generic_to_shared(&smem[warp][0][0][0]);
    const float* __restrict__ r0p = R + (size_t)row0 * NN;
    const float* __restrict__ r1p = r0p + NN;
    const float4* __restrict__ xp = (const float4*)g_buf[pi];

    // Prologue: stages 0..NSLOT-1 in flight (one group per stage).
#pragma unroll
    for (int s = 0; s < NSLOT; s++) {
        uint32_t sb = sbase + (uint32_t)s * (2 * CPS * 4);
#pragma unroll
        for (int k = 0; k < 2; k++) {
            int c = lane + 32 * k;                       // chunk 0..63
            cp16(sb + c * 16,           r0p + s * CPS + c * 4);
            cp16(sb + CPS * 4 + c * 16, r1p + s * CPS + c * 4);
        }
        cp_commit();
    }

    float a0x = 0.f, a0y = 0.f, a0z = 0.f, a0w = 0.f;
    float a1x = 0.f, a1y = 0.f, a1z = 0.f, a1w = 0.f;

    int slot = 0;
#pragma unroll 1
    for (int s = 0; s < NSTAGE; s++) {
        cp_wait2();                      // stage s landed (<=2 groups pending)
        const float4* sm = &smem[warp][slot][0][0];
#pragma unroll
        for (int k = 0; k < 2; k++) {
            int c = lane + 32 * k;
            float4 b  = __ldg(xp + s * (CPS / 4) + c);   // L1-resident x
            float4 a0 = sm[c];
            float4 a1 = sm[CPS / 4 + c];
            a0x += a0.x * b.x;  a0y += a0.y * b.y;
            a0z += a0.z * b.z;  a0w += a0.w * b.w;
            a1x += a1.x * b.x;  a1y += a1.y * b.y;
            a1z += a1.z * b.z;  a1w += a1.w * b.w;
        }
        // Refill this slot with stage s+NSLOT (commit every iteration to
        // keep the one-group-per-iteration accounting exact).
        if (s + NSLOT < NSTAGE) {
            uint32_t sb = sbase + (uint32_t)slot * (2 * CPS * 4);
            int sc = (s + NSLOT) * CPS;
#pragma unroll
            for (int k = 0; k < 2; k++) {
                int c = lane + 32 * k;
                cp16(sb + c * 16,           r0p + sc + c * 4);
                cp16(sb + CPS * 4 + c * 16, r1p + sc + c * 4);
            }
        }
        cp_commit();
        slot = (slot + 1 == NSLOT) ? 0 : slot + 1;
    }

    float s0 = (a0x + a0y) + (a0z + a0w);
    float s1 = (a1x + a1y) + (a1z + a1w);
#pragma unroll
    for (int o = 16; o; o >>= 1) {
        s0 += __shfl_xor_sync(0xFFFFFFFFu, s0, o);
        s1 += __shfl_xor_sync(0xFFFFFFFFu, s1, o);
    }

    if (lane == 0) {
        float v0 = fminf(fmaxf(s0, 0.0f), 1.0f);
        float v1 = fminf(fmaxf(s1, 0.0f), 1.0f);
        g_buf[ni][row0]     = v0;
        g_buf[ni][row0 + 1] = v1;
        float p0  = g_buf[pi][row0],  p1  = g_buf[pi][row0 + 1];
        float pp0 = g_buf[ppi][row0], pp1 = g_buf[ppi][row0 + 1];
        int bad1 = (fabsf(v0 - p0)  > ATOL + RTOL * fabsf(p0)) |
                   (fabsf(v1 - p1)  > ATOL + RTOL * fabsf(p1));
        int bad2 = (fabsf(v0 - pp0) > ATOL + RTOL * fabsf(pp0)) |
                   (fabsf(v1 - pp1) > ATOL + RTOL * fabsf(pp1));
        if (bad1) atomicOr(&g_viol1, 1);
        if (bad2) atomicOr(&g_viol2, 1);
    }
}

// Per-step status update (frozen-carry semantics of the reference scan).
__global__ void update_step(int k, int ni) {
    if (g_status == 0) {
        g_steps = k;
        g_final = ni;
        if (g_viol1 == 0)                g_status = 1;  // PROVEN (priority)
        else if (k >= 2 && g_viol2 == 0) g_status = 2;  // GODEL
    }
    g_viol1 = 0;
    g_viol2 = 0;
}

__global__ void __launch_bounds__(256) final_kernel(float* __restrict__ out,
                                                    int out_size) {
    int idx = blockIdx.x * 256 + threadIdx.x;   // grid 32x256 = 8192
    int fi = g_final;
    if (idx < NN && idx < out_size) out[idx] = g_buf[fi][idx];
    if (idx == 0 && out_size >= NN + 2) {
        int st = g_status;
        out[NN]     = (float)(st == 0 ? 3 : st);   // TIMEOUT fixup
        out[NN + 1] = (float)g_steps;
    }
}

extern "C" void kernel_launch(void* const* d_in, const int* in_sizes, int n_in,
                              void* d_out, int out_size) {
    const float* R  = (const float*)d_in[0];
    const float* sv = (const float*)d_in[1];
    float* out = (float*)d_out;

    init_kernel<<<32, 256>>>(sv);
    for (int k = 1; k <= MAXS; k++) {
        int pi  = (k - 1) % 3;   // prev
        int ppi = (k + 1) % 3;   // pprev  ((k-2) mod 3, kept non-negative)
        int ni  = k % 3;         // next
        gemv_step<<<1024, 128>>>(R, pi, ppi, ni);
        update_step<<<1, 1>>>(k, ni);
    }
    final_kernel<<<32, 256>>>(out, out_size);
}

// round 15
// speedup vs baseline: 1.5307x; 1.1609x over previous
#include <cuda_runtime.h>
#include <cuda_bf16.h>
#include <cstddef>
#include <cstdint>

// GodelToposEngine: next = clamp(R @ prev, 0, 1), up to 20 steps.
// status: 1=PROVEN (next==prev), 2=GODEL (next==pprev, step>=2), 3=TIMEOUT.
// allclose: |a-b| <= atol + rtol*|b|, atol=1e-4, rtol=1e-5 (b = second arg).

#define NN 8192
#define MAXS 20
#define ATOL 1e-4f
#define RTOL 1e-5f

#define CPS 256                 // columns per pipeline stage (floats)
#define NSTAGE (NN / CPS)       // 32 stages
#define NSLOT 3                 // ring depth (wait_group 2)

// Triple-buffered state vectors + control scalars (no allocation allowed).
__device__ float g_buf[3][NN];
__device__ int g_status;
__device__ int g_steps;
__device__ int g_final;   // which buffer holds the final state
__device__ int g_viol1;   // any element violates allclose(next, prev)
__device__ int g_viol2;   // any element violates allclose(next, pprev)

__global__ void __launch_bounds__(256) init_kernel(const float* __restrict__ sv) {
    int idx = blockIdx.x * 256 + threadIdx.x;   // grid 32x256 = 8192
    float v = sv[idx];
    g_buf[0][idx] = v;   // prev  for step 1
    g_buf[2][idx] = v;   // pprev for step 1
    if (idx == 0) {
        g_status = 0;
        g_steps = 0;
        g_final = 2;
        g_viol1 = 0;
        g_viol2 = 0;
    }
}

__device__ __forceinline__ void cp16(uint32_t dst, const float* src) {
    // .cg: L2-normal (no evict-first) — inter-step L2 retention is the point.
    asm volatile("cp.async.cg.shared.global [%0], [%1], 16;" :: "r"(dst), "l"(src));
}
__device__ __forceinline__ void cp_commit() {
    asm volatile("cp.async.commit_group;" ::: "memory");
}
__device__ __forceinline__ void cp_wait2() {
    asm volatile("cp.async.wait_group 2;" ::: "memory");
}

// One step: GEMV + clamp + convergence flags. Launch shape frozen from R14
// (1024 x 128, warp owns 2 rows, 3-slot cp.async ring, barrier-free).
// NEW: `rev` flips the column-sweep direction per step. All blocks sweep
// columns together (one uniform wave), so step k leaves the LAST ~126 MB of
// columns resident in L2; step k+1 sweeping the opposite direction hits L2
// for ~49% of its reads instead of thrashing. Dot product is commutative —
// only fp32 summation order changes (same noise class as measured 2.5e-6).
__global__ void __launch_bounds__(128, 8) gemv_step(const float* __restrict__ R,
                                                    int pi, int ppi, int ni,
                                                    int rev) {
    if (g_status != 0) return;   // frozen: skip all work

    // [warp][slot][row][chunk] : 4*3*2*64 float4 = 24576 B
    __shared__ float4 smem[4][NSLOT][2][CPS / 4];

    const int tid  = threadIdx.x;
    const int warp = tid >> 5;
    const int lane = tid & 31;
    const int w    = blockIdx.x * 4 + warp;   // [0, 4096)
    const int row0 = 2 * w;

    const uint32_t sbase =
        (uint32_t)__cvta_generic_to_shared(&smem[warp][0][0][0]);
    const float* __restrict__ r0p = R + (size_t)row0 * NN;
    const float* __restrict__ r1p = r0p + NN;
    const float4* __restrict__ xp = (const float4*)g_buf[pi];

    // Prologue: pipeline stages 0..NSLOT-1 in flight (one group per stage).
#pragma unroll
    for (int s = 0; s < NSLOT; s++) {
        int cs = rev ? (NSTAGE - 1 - s) : s;            // logical -> column stage
        uint32_t sb = sbase + (uint32_t)s * (2 * CPS * 4);
#pragma unroll
        for (int k = 0; k < 2; k++) {
            int c = lane + 32 * k;                      // chunk 0..63
            cp16(sb + c * 16,           r0p + cs * CPS + c * 4);
            cp16(sb + CPS * 4 + c * 16, r1p + cs * CPS + c * 4);
        }
        cp_commit();
    }

    float a0x = 0.f, a0y = 0.f, a0z = 0.f, a0w = 0.f;
    float a1x = 0.f, a1y = 0.f, a1z = 0.f, a1w = 0.f;

    int slot = 0;
#pragma unroll 1
    for (int s = 0; s < NSTAGE; s++) {
        cp_wait2();                      // stage s landed (<=2 groups pending)
        int cs = rev ? (NSTAGE - 1 - s) : s;
        const float4* sm = &smem[warp][slot][0][0];
#pragma unroll
        for (int k = 0; k < 2; k++) {
            int c = lane + 32 * k;
            float4 b  = __ldg(xp + cs * (CPS / 4) + c);  // L1-resident x
            float4 a0 = sm[c];
            float4 a1 = sm[CPS / 4 + c];
            a0x += a0.x * b.x;  a0y += a0.y * b.y;
            a0z += a0.z * b.z;  a0w += a0.w * b.w;
            a1x += a1.x * b.x;  a1y += a1.y * b.y;
            a1z += a1.z * b.z;  a1w += a1.w * b.w;
        }
        // Refill this slot with logical stage s+NSLOT (commit every
        // iteration to keep the one-group-per-iteration accounting exact).
        if (s + NSLOT < NSTAGE) {
            int cr = rev ? (NSTAGE - 1 - (s + NSLOT)) : (s + NSLOT);
            uint32_t sb = sbase + (uint32_t)slot * (2 * CPS * 4);
#pragma unroll
            for (int k = 0; k < 2; k++) {
                int c = lane + 32 * k;
                cp16(sb + c * 16,           r0p + cr * CPS + c * 4);
                cp16(sb + CPS * 4 + c * 16, r1p + cr * CPS + c * 4);
            }
        }
        cp_commit();
        slot = (slot + 1 == NSLOT) ? 0 : slot + 1;
    }

    float s0 = (a0x + a0y) + (a0z + a0w);
    float s1 = (a1x + a1y) + (a1z + a1w);
#pragma unroll
    for (int o = 16; o; o >>= 1) {
        s0 += __shfl_xor_sync(0xFFFFFFFFu, s0, o);
        s1 += __shfl_xor_sync(0xFFFFFFFFu, s1, o);
    }

    if (lane == 0) {
        float v0 = fminf(fmaxf(s0, 0.0f), 1.0f);
        float v1 = fminf(fmaxf(s1, 0.0f), 1.0f);
        g_buf[ni][row0]     = v0;
        g_buf[ni][row0 + 1] = v1;
        float p0  = g_buf[pi][row0],  p1  = g_buf[pi][row0 + 1];
        float pp0 = g_buf[ppi][row0], pp1 = g_buf[ppi][row0 + 1];
        int bad1 = (fabsf(v0 - p0)  > ATOL + RTOL * fabsf(p0)) |
                   (fabsf(v1 - p1)  > ATOL + RTOL * fabsf(p1));
        int bad2 = (fabsf(v0 - pp0) > ATOL + RTOL * fabsf(pp0)) |
                   (fabsf(v1 - pp1) > ATOL + RTOL * fabsf(pp1));
        if (bad1) atomicOr(&g_viol1, 1);
        if (bad2) atomicOr(&g_viol2, 1);
    }
}

// Per-step status update (frozen-carry semantics of the reference scan).
__global__ void update_step(int k, int ni) {
    if (g_status == 0) {
        g_steps = k;
        g_final = ni;
        if (g_viol1 == 0)                g_status = 1;  // PROVEN (priority)
        else if (k >= 2 && g_viol2 == 0) g_status = 2;  // GODEL
    }
    g_viol1 = 0;
    g_viol2 = 0;
}

__global__ void __launch_bounds__(256) final_kernel(float* __restrict__ out,
                                                    int out_size) {
    int idx = blockIdx.x * 256 + threadIdx.x;   // grid 32x256 = 8192
    int fi = g_final;
    if (idx < NN && idx < out_size) out[idx] = g_buf[fi][idx];
    if (idx == 0 && out_size >= NN + 2) {
        int st = g_status;
        out[NN]     = (float)(st == 0 ? 3 : st);   // TIMEOUT fixup
        out[NN + 1] = (float)g_steps;
    }
}

extern "C" void kernel_launch(void* const* d_in, const int* in_sizes, int n_in,
                              void* d_out, int out_size) {
    const float* R  = (const float*)d_in[0];
    const float* sv = (const float*)d_in[1];
    float* out = (float*)d_out;

    init_kernel<<<32, 256>>>(sv);
    for (int k = 1; k <= MAXS; k++) {
        int pi  = (k - 1) % 3;   // prev
        int ppi = (k + 1) % 3;   // pprev  ((k-2) mod 3, kept non-negative)
        int ni  = k % 3;         // next
        int rev = (k - 1) & 1;   // step 1 forward, step 2 reverse, ...
        gemv_step<<<1024, 128>>>(R, pi, ppi, ni, rev);
        update_step<<<1, 1>>>(k, ni);
    }
    final_kernel<<<32, 256>>>(out, out_size);
}

// round 17
// speedup vs baseline: 1.5390x; 1.0054x over previous
#include <cuda_runtime.h>
#include <cuda_bf16.h>
#include <cstddef>
#include <cstdint>

// GodelToposEngine: next = clamp(R @ prev, 0, 1), up to 20 steps.
// status: 1=PROVEN (next==prev), 2=GODEL (next==pprev, step>=2), 3=TIMEOUT.
// allclose: |a-b| <= atol + rtol*|b|, atol=1e-4, rtol=1e-5 (b = second arg).

#define NN 8192
#define MAXS 20
#define ATOL 1e-4f
#define RTOL 1e-5f

#define CPS 256                 // columns per pipeline stage (floats)
#define NSTAGE (NN / CPS)       // 32 stages
#define NSLOT 3                 // ring depth (wait_group 2)

// Triple-buffered state vectors + control scalars (no allocation allowed).
__device__ float g_buf[3][NN];
__device__ int g_status;
__device__ int g_steps;
__device__ int g_final;   // which buffer holds the final state
__device__ int g_viol1;   // any element violates allclose(next, prev)
__device__ int g_viol2;   // any element violates allclose(next, pprev)

__global__ void __launch_bounds__(256) init_kernel(const float* __restrict__ sv) {
    int idx = blockIdx.x * 256 + threadIdx.x;   // grid 32x256 = 8192
    float v = sv[idx];
    g_buf[0][idx] = v;   // prev  for step 1
    g_buf[2][idx] = v;   // pprev for step 1
    if (idx == 0) {
        g_status = 0;
        g_steps = 0;
        g_final = 2;
        g_viol1 = 0;
        g_viol2 = 0;
    }
}

__device__ __forceinline__ void cp16(uint32_t dst, const float* src) {
    // .cg: L2-normal (no evict-first) — inter-step L2 retention is the point.
    asm volatile("cp.async.cg.shared.global [%0], [%1], 16;" :: "r"(dst), "l"(src));
}
__device__ __forceinline__ void cp_commit() {
    asm volatile("cp.async.commit_group;" ::: "memory");
}
__device__ __forceinline__ void cp_wait2() {
    asm volatile("cp.async.wait_group 2;" ::: "memory");
}

// One step: GEMV + clamp + convergence flags. Launch shape frozen from R14
// (1024 x 128, warp owns 2 rows, 3-slot cp.async ring, barrier-free).
// NEW: `rev` flips the column-sweep direction per step. All blocks sweep
// columns together (one uniform wave), so step k leaves the LAST ~126 MB of
// columns resident in L2; step k+1 sweeping the opposite direction hits L2
// for ~49% of its reads instead of thrashing. Dot product is commutative —
// only fp32 summation order changes (same noise class as measured 2.5e-6).
__global__ void __launch_bounds__(128, 8) gemv_step(const float* __restrict__ R,
                                                    int pi, int ppi, int ni,
                                                    int rev) {
    if (g_status != 0) return;   // frozen: skip all work

    // [warp][slot][row][chunk] : 4*3*2*64 float4 = 24576 B
    __shared__ float4 smem[4][NSLOT][2][CPS / 4];

    const int tid  = threadIdx.x;
    const int warp = tid >> 5;
    const int lane = tid & 31;
    const int w    = blockIdx.x * 4 + warp;   // [0, 4096)
    const int row0 = 2 * w;

    const uint32_t sbase =
        (uint32_t)__cvta_generic_to_shared(&smem[warp][0][0][0]);
    const float* __restrict__ r0p = R + (size_t)row0 * NN;
    const float* __restrict__ r1p = r0p + NN;
    const float4* __restrict__ xp = (const float4*)g_buf[pi];

    // Prologue: pipeline stages 0..NSLOT-1 in flight (one group per stage).
#pragma unroll
    for (int s = 0; s < NSLOT; s++) {
        int cs = rev ? (NSTAGE - 1 - s) : s;            // logical -> column stage
        uint32_t sb = sbase + (uint32_t)s * (2 * CPS * 4);
#pragma unroll
        for (int k = 0; k < 2; k++) {
            int c = lane + 32 * k;                      // chunk 0..63
            cp16(sb + c * 16,           r0p + cs * CPS + c * 4);
            cp16(sb + CPS * 4 + c * 16, r1p + cs * CPS + c * 4);
        }
        cp_commit();
    }

    float a0x = 0.f, a0y = 0.f, a0z = 0.f, a0w = 0.f;
    float a1x = 0.f, a1y = 0.f, a1z = 0.f, a1w = 0.f;

    int slot = 0;
#pragma unroll 1
    for (int s = 0; s < NSTAGE; s++) {
        cp_wait2();                      // stage s landed (<=2 groups pending)
        int cs = rev ? (NSTAGE - 1 - s) : s;
        const float4* sm = &smem[warp][slot][0][0];
#pragma unroll
        for (int k = 0; k < 2; k++) {
            int c = lane + 32 * k;
            float4 b  = __ldg(xp + cs * (CPS / 4) + c);  // L1-resident x
            float4 a0 = sm[c];
            float4 a1 = sm[CPS / 4 + c];
            a0x += a0.x * b.x;  a0y += a0.y * b.y;
            a0z += a0.z * b.z;  a0w += a0.w * b.w;
            a1x += a1.x * b.x;  a1y += a1.y * b.y;
            a1z += a1.z * b.z;  a1w += a1.w * b.w;
        }
        // Refill this slot with logical stage s+NSLOT (commit every
        // iteration to keep the one-group-per-iteration accounting exact).
        if (s + NSLOT < NSTAGE) {
            int cr = rev ? (NSTAGE - 1 - (s + NSLOT)) : (s + NSLOT);
            uint32_t sb = sbase + (uint32_t)slot * (2 * CPS * 4);
#pragma unroll
            for (int k = 0; k < 2; k++) {
                int c = lane + 32 * k;
                cp16(sb + c * 16,           r0p + cr * CPS + c * 4);
                cp16(sb + CPS * 4 + c * 16, r1p + cr * CPS + c * 4);
            }
        }
        cp_commit();
        slot = (slot + 1 == NSLOT) ? 0 : slot + 1;
    }

    float s0 = (a0x + a0y) + (a0z + a0w);
    float s1 = (a1x + a1y) + (a1z + a1w);
#pragma unroll
    for (int o = 16; o; o >>= 1) {
        s0 += __shfl_xor_sync(0xFFFFFFFFu, s0, o);
        s1 += __shfl_xor_sync(0xFFFFFFFFu, s1, o);
    }

    if (lane == 0) {
        float v0 = fminf(fmaxf(s0, 0.0f), 1.0f);
        float v1 = fminf(fmaxf(s1, 0.0f), 1.0f);
        g_buf[ni][row0]     = v0;
        g_buf[ni][row0 + 1] = v1;
        float p0  = g_buf[pi][row0],  p1  = g_buf[pi][row0 + 1];
        float pp0 = g_buf[ppi][row0], pp1 = g_buf[ppi][row0 + 1];
        int bad1 = (fabsf(v0 - p0)  > ATOL + RTOL * fabsf(p0)) |
                   (fabsf(v1 - p1)  > ATOL + RTOL * fabsf(p1));
        int bad2 = (fabsf(v0 - pp0) > ATOL + RTOL * fabsf(pp0)) |
                   (fabsf(v1 - pp1) > ATOL + RTOL * fabsf(pp1));
        if (bad1) atomicOr(&g_viol1, 1);
        if (bad2) atomicOr(&g_viol2, 1);
    }
}

// Per-step status update (frozen-carry semantics of the reference scan).
__global__ void update_step(int k, int ni) {
    if (g_status == 0) {
        g_steps = k;
        g_final = ni;
        if (g_viol1 == 0)                g_status = 1;  // PROVEN (priority)
        else if (k >= 2 && g_viol2 == 0) g_status = 2;  // GODEL
    }
    g_viol1 = 0;
    g_viol2 = 0;
}

__global__ void __launch_bounds__(256) final_kernel(float* __restrict__ out,
                                                    int out_size) {
    int idx = blockIdx.x * 256 + threadIdx.x;   // grid 32x256 = 8192
    int fi = g_final;
    if (idx < NN && idx < out_size) out[idx] = g_buf[fi][idx];
    if (idx == 0 && out_size >= NN + 2) {
        int st = g_status;
        out[NN]     = (float)(st == 0 ? 3 : st);   // TIMEOUT fixup
        out[NN + 1] = (float)g_steps;
    }
}

extern "C" void kernel_launch(void* const* d_in, const int* in_sizes, int n_in,
                              void* d_out, int out_size) {
    const float* R  = (const float*)d_in[0];
    const float* sv = (const float*)d_in[1];
    float* out = (float*)d_out;

    init_kernel<<<32, 256>>>(sv);
    for (int k = 1; k <= MAXS; k++) {
        int pi  = (k - 1) % 3;   // prev
        int ppi = (k + 1) % 3;   // pprev  ((k-2) mod 3, kept non-negative)
        int ni  = k % 3;         // next
        int rev = (k - 1) & 1;   // step 1 forward, step 2 reverse, ...
        gemv_step<<<1024, 128>>>(R, pi, ppi, ni, rev);
        update_step<<<1, 1>>>(k, ni);
    }
    final_kernel<<<32, 256>>>(out, out_size);
}